// round 4
// baseline (speedup 1.0000x reference)
#include <cuda_runtime.h>
#include <cuda_bf16.h>

// Shape (fixed): words (32, 4096, 768) f32, diff (32,4096) [unused],
// W (1,1536) f32, b (1,) f32 -> out (32,1) f32.
#define B 32
#define L 4096
#define H 768
#define TWOH 1536
#define NEGV (-1e30f)

// Chunking: each block owns R rows of one batch.
#define CHUNKS 64               // chunks per batch
#define R (L / CHUNKS)          // 64 rows per chunk
#define NCHUNK (B * CHUNKS)     // 2048 blocks

// Per-chunk exports + completion ticket.
__device__ float g_cmax[NCHUNK];
__device__ float g_stail[NCHUNK * 5];
__device__ float g_thead[NCHUNK * 5];
__device__ unsigned int g_ticket = 0;

// ---------------------------------------------------------------------------
// Single fused kernel:
//   phase 1 (all blocks): s/t projections (warp-per-row-pair, float4
//     streaming, 12 loads in flight), internal windowed max, boundary exports.
//   phase 2 (last block via ticket): combine chunk maxes + boundary pairs +
//     bias/relu -> out[32].
// Boundary pairs between chunk c and c+1: l = R-5+i (tail i), l+k = R+j
// (head j), k = 5-i+j in [1,5]  <=>  j <= i.
// ---------------------------------------------------------------------------
__global__ __launch_bounds__(256) void ww_fused_kernel(
    const float* __restrict__ words,
    const float* __restrict__ W,
    const float* __restrict__ bias,
    float* __restrict__ out)
{
    __shared__ float sw[TWOH];       // w1 | w2
    __shared__ float s_sh[R];
    __shared__ float t_sh[R];
    __shared__ float red[8];
    __shared__ unsigned int s_last;

    for (int i = threadIdx.x; i < TWOH; i += blockDim.x) sw[i] = W[i];
    __syncthreads();

    const float4* w1v = reinterpret_cast<const float4*>(sw);
    const float4* w2v = reinterpret_cast<const float4*>(sw + H);

    const int c    = blockIdx.x;          // chunk id, 0..NCHUNK-1
    const int b    = c / CHUNKS;
    const int ch   = c % CHUNKS;
    const int row0 = b * L + ch * R;

    const int warp = threadIdx.x >> 5;
    const int lane = threadIdx.x & 31;

    // 8 warps; each warp handles 8 rows as 4 pairs (r, r+8) for doubled MLP
    // and pipelined reductions.
#pragma unroll
    for (int it = 0; it < R / 16; it++) {          // 4 iterations
        const int ra = warp + it * 16;             // first row of pair
        const int rb = ra + 8;                     // second row of pair
        const float4* wpa = reinterpret_cast<const float4*>(
            words + (size_t)(row0 + ra) * H);
        const float4* wpb = reinterpret_cast<const float4*>(
            words + (size_t)(row0 + rb) * H);

        float sa = 0.f, ta = 0.f, sb = 0.f, tb = 0.f;
#pragma unroll
        for (int i = 0; i < H / 128; i++) {        // 6 steps, 2x512B/warp/step
            const int idx = lane + i * 32;
            const float4 va = __ldcs(wpa + idx);   // read-once streaming
            const float4 vb = __ldcs(wpb + idx);
            const float4 a  = w1v[idx];
            const float4 b2 = w2v[idx];
            sa = fmaf(va.x, a.x,  fmaf(va.y, a.y,  fmaf(va.z, a.z,  fmaf(va.w, a.w,  sa))));
            ta = fmaf(va.x, b2.x, fmaf(va.y, b2.y, fmaf(va.z, b2.z, fmaf(va.w, b2.w, ta))));
            sb = fmaf(vb.x, a.x,  fmaf(vb.y, a.y,  fmaf(vb.z, a.z,  fmaf(vb.w, a.w,  sb))));
            tb = fmaf(vb.x, b2.x, fmaf(vb.y, b2.y, fmaf(vb.z, b2.z, fmaf(vb.w, b2.w, tb))));
        }
        // 4 independent shuffle-reduction chains pipeline together.
#pragma unroll
        for (int off = 16; off > 0; off >>= 1) {
            sa += __shfl_xor_sync(0xFFFFFFFFu, sa, off);
            ta += __shfl_xor_sync(0xFFFFFFFFu, ta, off);
            sb += __shfl_xor_sync(0xFFFFFFFFu, sb, off);
            tb += __shfl_xor_sync(0xFFFFFFFFu, tb, off);
        }
        if (lane == 0) {
            s_sh[ra] = sa;  t_sh[ra] = ta;
            s_sh[rb] = sb;  t_sh[rb] = tb;
        }
    }
    __syncthreads();

    // Internal windowed max: threads 0..R-1 each take one l.
    float m = NEGV;
    if (threadIdx.x < R) {
        const int l = threadIdx.x;
        const float sl = s_sh[l];
#pragma unroll
        for (int k = 1; k <= 5; k++)
            if (l + k < R) m = fmaxf(m, sl + t_sh[l + k]);
    }
#pragma unroll
    for (int off = 16; off > 0; off >>= 1)
        m = fmaxf(m, __shfl_xor_sync(0xFFFFFFFFu, m, off));
    if (lane == 0) red[warp] = m;
    __syncthreads();
    if (threadIdx.x == 0) {
        float mm = red[0];
#pragma unroll
        for (int w = 1; w < 8; w++) mm = fmaxf(mm, red[w]);
        g_cmax[c] = mm;
    }
    if (threadIdx.x < 5) {
        g_thead[c * 5 + threadIdx.x] = t_sh[threadIdx.x];
        g_stail[c * 5 + threadIdx.x] = s_sh[R - 5 + threadIdx.x];
    }
    __syncthreads();

    // --- ticket: last block to finish does the final reduction ---
    if (threadIdx.x == 0) {
        __threadfence();
        s_last = atomicAdd(&g_ticket, 1u);
    }
    __syncthreads();
    if (s_last != NCHUNK - 1) return;
    __threadfence();   // acquire: see all blocks' exports

    // Final reduction: 256 threads = 32 batches x 8 threads.
    // Each thread handles CHUNKS/8 = 8 chunks of its batch.
    {
        const int fb  = threadIdx.x >> 3;   // batch 0..31
        const int sub = threadIdx.x & 7;    // 0..7
        float fm = NEGV;
#pragma unroll
        for (int q = 0; q < CHUNKS / 8; q++) {
            const int lc = sub * (CHUNKS / 8) + q;      // local chunk
            const int cc = fb * CHUNKS + lc;
            fm = fmaxf(fm, g_cmax[cc]);
            if (lc < CHUNKS - 1) {
#pragma unroll
                for (int i = 0; i < 5; i++) {
                    const float st = g_stail[cc * 5 + i];
#pragma unroll
                    for (int j = 0; j < 5; j++)
                        if (j <= i)
                            fm = fmaxf(fm, st + g_thead[(cc + 1) * 5 + j]);
                }
            }
        }
        // reduce across the 8 threads of this batch (contiguous lanes)
#pragma unroll
        for (int off = 4; off > 0; off >>= 1)
            fm = fmaxf(fm, __shfl_xor_sync(0xFFFFFFFFu, fm, off));
        if (sub == 0)
            out[fb] = fmaxf(0.0f, fm + bias[0]);
    }
    __syncthreads();
    if (threadIdx.x == 0) g_ticket = 0;     // reset for next graph replay
}

extern "C" void kernel_launch(void* const* d_in, const int* in_sizes, int n_in,
                              void* d_out, int out_size)
{
    const float* words = (const float*)d_in[0];
    // d_in[1] = diff : unused by the reference computation
    const float* W     = (const float*)d_in[2];
    const float* bias  = (const float*)d_in[3];
    float* out         = (float*)d_out;

    ww_fused_kernel<<<NCHUNK, 256>>>(words, W, bias, out);
}

// round 5
// speedup vs baseline: 1.1030x; 1.1030x over previous
#include <cuda_runtime.h>
#include <cuda_bf16.h>

// Shape (fixed): words (32, 4096, 768) f32, diff (32,4096) [unused],
// W (1,1536) f32, b (1,) f32 -> out (32,1) f32.
#define B 32
#define L 4096
#define H 768
#define TWOH 1536
#define NEGV (-1e30f)

// Chunking: each block owns R rows of one batch.
#define CHUNKS 64               // chunks per batch
#define R (L / CHUNKS)          // 64 rows per chunk
#define NCHUNK (B * CHUNKS)     // 2048 blocks

// Per-chunk exports + completion ticket.
__device__ float g_cmax[NCHUNK];
__device__ float g_stail[NCHUNK * 5];
__device__ float g_thead[NCHUNK * 5];
__device__ unsigned int g_ticket = 0;

// ---------------------------------------------------------------------------
// Single fused kernel (R2 projection loop + R3 ticket finisher):
//   phase 1 (all blocks): s/t projections (warp-per-row, float4 streaming,
//     regs<=32), internal windowed max, boundary exports.
//   phase 2 (last block via ticket): combine chunk maxes + boundary pairs +
//     bias/relu -> out[32].
// Boundary pairs between chunk c and c+1: l = R-5+i (tail i), l+k = R+j
// (head j), k = 5-i+j in [1,5]  <=>  j <= i.
// ---------------------------------------------------------------------------
__global__ __launch_bounds__(256) void ww_fused_kernel(
    const float* __restrict__ words,
    const float* __restrict__ W,
    const float* __restrict__ bias,
    float* __restrict__ out)
{
    __shared__ float sw[TWOH];       // w1 | w2
    __shared__ float s_sh[R];
    __shared__ float t_sh[R];
    __shared__ float red[8];
    __shared__ unsigned int s_last;

    for (int i = threadIdx.x; i < TWOH; i += blockDim.x) sw[i] = W[i];
    __syncthreads();

    const float4* w1v = reinterpret_cast<const float4*>(sw);
    const float4* w2v = reinterpret_cast<const float4*>(sw + H);

    const int c    = blockIdx.x;          // chunk id, 0..NCHUNK-1
    const int b    = c / CHUNKS;
    const int ch   = c % CHUNKS;
    const int row0 = b * L + ch * R;

    const int warp = threadIdx.x >> 5;
    const int lane = threadIdx.x & 31;

    // 8 warps x 8 rows each (single row per warp iteration: regs <= 32,
    // one contiguous 3KB load stream per warp -> max occupancy + coalescing).
    for (int r = warp; r < R; r += 8) {
        const float4* wp = reinterpret_cast<const float4*>(
            words + (size_t)(row0 + r) * H);
        float s = 0.f, t = 0.f;
#pragma unroll
        for (int i = 0; i < H / 128; i++) {        // 6 steps, 512B/warp/step
            const int idx = lane + i * 32;
            const float4 v  = __ldcs(wp + idx);    // read-once streaming
            const float4 a  = w1v[idx];
            const float4 b2 = w2v[idx];
            s = fmaf(v.x, a.x,  fmaf(v.y, a.y,  fmaf(v.z, a.z,  fmaf(v.w, a.w,  s))));
            t = fmaf(v.x, b2.x, fmaf(v.y, b2.y, fmaf(v.z, b2.z, fmaf(v.w, b2.w, t))));
        }
#pragma unroll
        for (int off = 16; off > 0; off >>= 1) {
            s += __shfl_xor_sync(0xFFFFFFFFu, s, off);
            t += __shfl_xor_sync(0xFFFFFFFFu, t, off);
        }
        if (lane == 0) {
            s_sh[r] = s;
            t_sh[r] = t;
        }
    }
    __syncthreads();

    // Internal windowed max: threads 0..R-1 each take one l.
    float m = NEGV;
    if (threadIdx.x < R) {
        const int l = threadIdx.x;
        const float sl = s_sh[l];
#pragma unroll
        for (int k = 1; k <= 5; k++)
            if (l + k < R) m = fmaxf(m, sl + t_sh[l + k]);
    }
#pragma unroll
    for (int off = 16; off > 0; off >>= 1)
        m = fmaxf(m, __shfl_xor_sync(0xFFFFFFFFu, m, off));
    if (lane == 0) red[warp] = m;
    __syncthreads();
    if (threadIdx.x == 0) {
        float mm = red[0];
#pragma unroll
        for (int w = 1; w < 8; w++) mm = fmaxf(mm, red[w]);
        g_cmax[c] = mm;
    }
    if (threadIdx.x < 5) {
        g_thead[c * 5 + threadIdx.x] = t_sh[threadIdx.x];
        g_stail[c * 5 + threadIdx.x] = s_sh[R - 5 + threadIdx.x];
    }
    __syncthreads();

    // --- ticket: last block to finish does the final reduction ---
    if (threadIdx.x == 0) {
        __threadfence();
        s_last = atomicAdd(&g_ticket, 1u);
    }
    __syncthreads();
    if (s_last != NCHUNK - 1) return;
    __threadfence();   // acquire: see all blocks' exports

    // Final reduction: 256 threads = 32 batches x 8 threads.
    // Each thread handles CHUNKS/8 = 8 chunks of its batch.
    {
        const int fb  = threadIdx.x >> 3;   // batch 0..31
        const int sub = threadIdx.x & 7;    // 0..7
        float fm = NEGV;
#pragma unroll
        for (int q = 0; q < CHUNKS / 8; q++) {
            const int lc = sub * (CHUNKS / 8) + q;      // local chunk
            const int cc = fb * CHUNKS + lc;
            fm = fmaxf(fm, g_cmax[cc]);
            if (lc < CHUNKS - 1) {
#pragma unroll
                for (int i = 0; i < 5; i++) {
                    const float st = g_stail[cc * 5 + i];
#pragma unroll
                    for (int j = 0; j < 5; j++)
                        if (j <= i)
                            fm = fmaxf(fm, st + g_thead[(cc + 1) * 5 + j]);
                }
            }
        }
        // reduce across the 8 threads of this batch (contiguous lanes)
#pragma unroll
        for (int off = 4; off > 0; off >>= 1)
            fm = fmaxf(fm, __shfl_xor_sync(0xFFFFFFFFu, fm, off));
        if (sub == 0)
            out[fb] = fmaxf(0.0f, fm + bias[0]);
    }
    __syncthreads();
    if (threadIdx.x == 0) g_ticket = 0;     // reset for next graph replay
}

extern "C" void kernel_launch(void* const* d_in, const int* in_sizes, int n_in,
                              void* d_out, int out_size)
{
    const float* words = (const float*)d_in[0];
    // d_in[1] = diff : unused by the reference computation
    const float* W     = (const float*)d_in[2];
    const float* bias  = (const float*)d_in[3];
    float* out         = (float*)d_out;

    ww_fused_kernel<<<NCHUNK, 256>>>(words, W, bias, out);
}

// round 6
// speedup vs baseline: 1.1735x; 1.0639x over previous
#include <cuda_runtime.h>
#include <cuda_bf16.h>

// Shape (fixed): words (32, 4096, 768) f32, diff (32,4096) [unused],
// W (1,1536) f32, b (1,) f32 -> out (32,1) f32.
#define B 32
#define L 4096
#define H 768
#define TWOH 1536
#define NEGV (-1e30f)

// Chunking: each block owns R rows of one batch.
#define CHUNKS 64               // chunks per batch
#define R (L / CHUNKS)          // 64 rows per chunk
#define NCHUNK (B * CHUNKS)     // 2048 blocks

// Per-chunk exports.
__device__ float g_cmax[NCHUNK];
__device__ float g_stail[NCHUNK * 5];
__device__ float g_thead[NCHUNK * 5];

// ---------------------------------------------------------------------------
// Kernel 1 (hot, pure: no atomics/fences): s/t projections (warp-per-row,
// float4 streaming, regs<=32), internal windowed max, boundary exports.
// ---------------------------------------------------------------------------
__global__ __launch_bounds__(256) void ww_fused_kernel(
    const float* __restrict__ words,
    const float* __restrict__ W)
{
    __shared__ float sw[TWOH];       // w1 | w2
    __shared__ float s_sh[R];
    __shared__ float t_sh[R];
    __shared__ float red[8];

    for (int i = threadIdx.x; i < TWOH; i += blockDim.x) sw[i] = W[i];
    __syncthreads();

    const float4* w1v = reinterpret_cast<const float4*>(sw);
    const float4* w2v = reinterpret_cast<const float4*>(sw + H);

    const int c    = blockIdx.x;          // chunk id, 0..NCHUNK-1
    const int b    = c / CHUNKS;
    const int ch   = c % CHUNKS;
    const int row0 = b * L + ch * R;

    const int warp = threadIdx.x >> 5;
    const int lane = threadIdx.x & 31;

    // 8 warps x 8 rows each: one contiguous 3KB stream per warp, regs <= 32.
    for (int r = warp; r < R; r += 8) {
        const float4* wp = reinterpret_cast<const float4*>(
            words + (size_t)(row0 + r) * H);
        float s = 0.f, t = 0.f;
#pragma unroll
        for (int i = 0; i < H / 128; i++) {        // 6 steps, 512B/warp/step
            const int idx = lane + i * 32;
            const float4 v  = __ldcs(wp + idx);    // read-once streaming
            const float4 a  = w1v[idx];
            const float4 b2 = w2v[idx];
            s = fmaf(v.x, a.x,  fmaf(v.y, a.y,  fmaf(v.z, a.z,  fmaf(v.w, a.w,  s))));
            t = fmaf(v.x, b2.x, fmaf(v.y, b2.y, fmaf(v.z, b2.z, fmaf(v.w, b2.w, t))));
        }
#pragma unroll
        for (int off = 16; off > 0; off >>= 1) {
            s += __shfl_xor_sync(0xFFFFFFFFu, s, off);
            t += __shfl_xor_sync(0xFFFFFFFFu, t, off);
        }
        if (lane == 0) {
            s_sh[r] = s;
            t_sh[r] = t;
        }
    }
    __syncthreads();

    // Internal windowed max: threads 0..R-1 each take one l.
    float m = NEGV;
    if (threadIdx.x < R) {
        const int l = threadIdx.x;
        const float sl = s_sh[l];
#pragma unroll
        for (int k = 1; k <= 5; k++)
            if (l + k < R) m = fmaxf(m, sl + t_sh[l + k]);
    }
#pragma unroll
    for (int off = 16; off > 0; off >>= 1)
        m = fmaxf(m, __shfl_xor_sync(0xFFFFFFFFu, m, off));
    if (lane == 0) red[warp] = m;
    __syncthreads();
    if (threadIdx.x == 0) {
        float mm = red[0];
#pragma unroll
        for (int w = 1; w < 8; w++) mm = fmaxf(mm, red[w]);
        g_cmax[c] = mm;
    }
    if (threadIdx.x < 5) {
        g_thead[c * 5 + threadIdx.x] = t_sh[threadIdx.x];
        g_stail[c * 5 + threadIdx.x] = s_sh[R - 5 + threadIdx.x];
    }
}

// ---------------------------------------------------------------------------
// Kernel 2 (finisher): one block per batch, 256 threads.
//   threads 0..63   : chunk maxes (one each)
//   threads 64..126 : boundary t (thread 64+q owns boundary q: 15 pairs)
// Boundary pairs chunk c -> c+1: l=R-5+i, l+k=R+j, k=5-i+j in [1,5] <=> j<=i.
// ---------------------------------------------------------------------------
__global__ __launch_bounds__(256) void ww_final_kernel(
    const float* __restrict__ bias,
    float* __restrict__ out)
{
    __shared__ float red[8];
    const int b  = blockIdx.x;
    const int t  = threadIdx.x;
    const int c0 = b * CHUNKS;

    float m = NEGV;
    if (t < CHUNKS) {
        m = g_cmax[c0 + t];
    } else if (t >= 64 && t < 64 + CHUNKS - 1) {
        const int c = c0 + (t - 64);
        // 10 independent loads (MLP=10), all L2-resident.
        float st[5], th[5];
#pragma unroll
        for (int i = 0; i < 5; i++) st[i] = g_stail[c * 5 + i];
#pragma unroll
        for (int j = 0; j < 5; j++) th[j] = g_thead[(c + 1) * 5 + j];
#pragma unroll
        for (int i = 0; i < 5; i++)
#pragma unroll
            for (int j = 0; j < 5; j++)
                if (j <= i) m = fmaxf(m, st[i] + th[j]);
    }

#pragma unroll
    for (int off = 16; off > 0; off >>= 1)
        m = fmaxf(m, __shfl_xor_sync(0xFFFFFFFFu, m, off));
    if ((t & 31) == 0) red[t >> 5] = m;
    __syncthreads();
    if (t == 0) {
        float mm = red[0];
#pragma unroll
        for (int w = 1; w < 8; w++) mm = fmaxf(mm, red[w]);
        out[b] = fmaxf(0.0f, mm + bias[0]);
    }
}

extern "C" void kernel_launch(void* const* d_in, const int* in_sizes, int n_in,
                              void* d_out, int out_size)
{
    const float* words = (const float*)d_in[0];
    // d_in[1] = diff : unused by the reference computation
    const float* W     = (const float*)d_in[2];
    const float* bias  = (const float*)d_in[3];
    float* out         = (float*)d_out;

    ww_fused_kernel<<<NCHUNK, 256>>>(words, W);
    ww_final_kernel<<<B, 256>>>(bias, out);
}